// round 14
// baseline (speedup 1.0000x reference)
#include <cuda_runtime.h>
#include <cuda_fp16.h>
#include <cstdint>

#define BB 8
#define CC 384
#define NNPX 1024
#define KEYS 16
#define HEADS 4
#define VS 96
#define OQ 64
#define OKCH 16
#define OT 176

__device__ float g_proj[BB * OT * NNPX];
__device__ float g_vT[BB * NNPX * VS];
__device__ float g_lamc4[BB * KEYS * VS * 4];
__device__ float g_bnsc[160];
__device__ float g_bnsh[160];
__device__ int   g_tile;
__device__ __align__(16) __half g_peA[16384 * 1024];  // [(n*16+k)][m]
__device__ __align__(16) __half g_vhf[768 * 1024];    // [(b*96+v)][m]

__device__ __forceinline__ uint32_t smem_u32(const void* p) {
    uint32_t a;
    asm("{ .reg .u64 t; cvta.to.shared.u64 t, %1; cvt.u32.u64 %0, t; }" : "=r"(a) : "l"(p));
    return a;
}
__device__ __forceinline__ void cp16(uint32_t d, const void* s) {
    asm volatile("cp.async.cg.shared.global [%0], [%1], 16;" :: "r"(d), "l"(s) : "memory");
}
__device__ __forceinline__ void cp_commit() { asm volatile("cp.async.commit_group;" ::: "memory"); }
template <int N> __device__ __forceinline__ void cp_wait() {
    asm volatile("cp.async.wait_group %0;" :: "n"(N) : "memory");
}
__device__ __forceinline__ void ldmx4(uint32_t* r, uint32_t a) {
    asm volatile("ldmatrix.sync.aligned.m8n8.x4.shared.b16 {%0,%1,%2,%3}, [%4];"
                 : "=r"(r[0]), "=r"(r[1]), "=r"(r[2]), "=r"(r[3]) : "r"(a));
}
__device__ __forceinline__ void mma16816(float* d, const uint32_t* a, uint32_t b0, uint32_t b1) {
    asm volatile("mma.sync.aligned.m16n8k16.row.col.f32.f16.f16.f32 "
                 "{%0,%1,%2,%3}, {%4,%5,%6,%7}, {%8,%9}, {%0,%1,%2,%3};"
                 : "+f"(d[0]), "+f"(d[1]), "+f"(d[2]), "+f"(d[3])
                 : "r"(a[0]), "r"(a[1]), "r"(a[2]), "r"(a[3]), "r"(b0), "r"(b1));
}
__device__ __forceinline__ unsigned long long fma2(unsigned long long a,
                                                   unsigned long long b,
                                                   unsigned long long c) {
    unsigned long long d;
    asm("fma.rn.f32x2 %0, %1, %2, %3;" : "=l"(d) : "l"(a), "l"(b), "l"(c));
    return d;
}
__device__ __forceinline__ unsigned long long pack2(float lo, float hi) {
    unsigned long long d;
    asm("mov.b64 %0, {%1, %2};" : "=l"(d) : "f"(lo), "f"(hi));
    return d;
}
__device__ __forceinline__ void unpack2(unsigned long long d, float& lo, float& hi) {
    asm("mov.b64 {%0, %1}, %2;" : "=f"(lo), "=f"(hi) : "l"(d));
}

// ===== K0: proj (f32x2-packed) =====
__global__ void __launch_bounds__(256) proj_kernel(
    const float* __restrict__ x, const float* __restrict__ Wq,
    const float* __restrict__ Wk, const float* __restrict__ Wv) {
    extern __shared__ float xs[];
    int b = blockIdx.x >> 4, n0 = (blockIdx.x & 15) << 6;
    const float* xb = x + (size_t)b * CC * NNPX;
    for (int i = threadIdx.x; i < CC * 16; i += 256) {
        int c = i >> 4, q4 = i & 15;
        ((float4*)xs)[i] = *(const float4*)(xb + (size_t)c * NNPX + n0 + q4 * 4);
    }
    __syncthreads();
    int nq = threadIdx.x & 15, og = threadIdx.x >> 4;
    const float* wp[11];
#pragma unroll
    for (int j = 0; j < 11; j++) {
        int o = og * 11 + j;
        wp[j] = (o < OQ) ? (Wq + (size_t)o * CC)
              : ((o < OQ + OKCH) ? (Wk + (size_t)(o - OQ) * CC)
                                 : (Wv + (size_t)(o - OQ - OKCH) * CC));
    }
    unsigned long long acc[11][2];
#pragma unroll
    for (int j = 0; j < 11; j++) acc[j][0] = acc[j][1] = 0ull;
    for (int c = 0; c < CC; c++) {
        float4 xv = *(const float4*)(xs + c * 64 + nq * 4);
        unsigned long long x01 = pack2(xv.x, xv.y);
        unsigned long long x23 = pack2(xv.z, xv.w);
#pragma unroll
        for (int j = 0; j < 11; j++) {
            float w = __ldg(wp[j] + c);
            unsigned long long ww = pack2(w, w);
            acc[j][0] = fma2(ww, x01, acc[j][0]);
            acc[j][1] = fma2(ww, x23, acc[j][1]);
        }
    }
#pragma unroll
    for (int j = 0; j < 11; j++) {
        int o = og * 11 + j;
        float4 v4;
        unpack2(acc[j][0], v4.x, v4.y);
        unpack2(acc[j][1], v4.z, v4.w);
        *(float4*)(g_proj + ((size_t)b * OT + o) * NNPX + n0 + nq * 4) = v4;
    }
}

// ===== K1: fused BN stats + softmax =====
__global__ void __launch_bounds__(256) bnsm_kernel(
    const float* __restrict__ gq, const float* __restrict__ bq,
    const float* __restrict__ gv, const float* __restrict__ bv) {
    if (blockIdx.x < 160) {
        int ch = blockIdx.x;
        int o = (ch < OQ) ? ch : (OQ + OKCH + (ch - OQ));
        float s = 0.f, s2 = 0.f;
        for (int i = threadIdx.x; i < BB * NNPX; i += 256) {
            int b = i >> 10, n = i & (NNPX - 1);
            float v = g_proj[((size_t)b * OT + o) * NNPX + n];
            s += v; s2 = fmaf(v, v, s2);
        }
        __shared__ float rs[8], rs2[8];
#pragma unroll
        for (int off = 16; off; off >>= 1) {
            s += __shfl_xor_sync(~0u, s, off);
            s2 += __shfl_xor_sync(~0u, s2, off);
        }
        if ((threadIdx.x & 31) == 0) { rs[threadIdx.x >> 5] = s; rs2[threadIdx.x >> 5] = s2; }
        __syncthreads();
        if (threadIdx.x == 0) {
            float S = 0.f, S2 = 0.f;
#pragma unroll
            for (int i = 0; i < 8; i++) { S += rs[i]; S2 += rs2[i]; }
            const float inv = 1.f / (float)(BB * NNPX);
            float mean = S * inv, var = S2 * inv - mean * mean;
            float g = (ch < OQ) ? gq[ch] : gv[ch - OQ];
            float be = (ch < OQ) ? bq[ch] : bv[ch - OQ];
            float sc = g * rsqrtf(var + 1e-5f);
            g_bnsc[ch] = sc;
            g_bnsh[ch] = be - mean * sc;
        }
    } else {
        int blk = blockIdx.x - 160;
        int b = blk >> 4, key = blk & 15;
        float* row = g_proj + ((size_t)b * OT + OQ + key) * NNPX;
        int t = threadIdx.x;
        float4 v = *(float4*)(row + t * 4);
        float mx = fmaxf(fmaxf(v.x, v.y), fmaxf(v.z, v.w));
        __shared__ float rbuf[8];
#pragma unroll
        for (int off = 16; off; off >>= 1) mx = fmaxf(mx, __shfl_xor_sync(~0u, mx, off));
        if ((t & 31) == 0) rbuf[t >> 5] = mx;
        __syncthreads();
        mx = rbuf[0];
#pragma unroll
        for (int i = 1; i < 8; i++) mx = fmaxf(mx, rbuf[i]);
        float e0 = expf(v.x - mx), e1 = expf(v.y - mx), e2 = expf(v.z - mx), e3 = expf(v.w - mx);
        float s = e0 + e1 + e2 + e3;
#pragma unroll
        for (int off = 16; off; off >>= 1) s += __shfl_xor_sync(~0u, s, off);
        __syncthreads();
        if ((t & 31) == 0) rbuf[t >> 5] = s;
        __syncthreads();
        float S = 0.f;
#pragma unroll
        for (int i = 0; i < 8; i++) S += rbuf[i];
        float inv = 1.f / S;
        *(float4*)(row + t * 4) = make_float4(e0 * inv, e1 * inv, e2 * inv, e3 * inv);
    }
}

// ===== K2: vT fp32 + fp16 B plane =====
__global__ void __launch_bounds__(256) vT_build() {
    int b = blockIdx.x >> 5, m0 = (blockIdx.x & 31) << 5;
    __shared__ float ts[32 * 97];
    for (int i = threadIdx.x; i < VS * 32; i += 256) {
        int v = i >> 5, mm = i & 31;
        float val = g_proj[((size_t)b * OT + OQ + OKCH + v) * NNPX + m0 + mm];
        ts[mm * 97 + v] = fmaf(val, g_bnsc[64 + v], g_bnsh[64 + v]);
    }
    __syncthreads();
    for (int j = threadIdx.x; j < 32 * VS; j += 256) {
        int mm = j / VS, v = j - mm * VS;
        g_vT[((size_t)b * NNPX + m0 + mm) * VS + v] = ts[mm * 97 + v];
    }
    for (int j = threadIdx.x; j < VS * 32; j += 256) {
        int v = j >> 5, mm = j & 31;
        g_vhf[((size_t)(b * VS + v)) * 1024 + m0 + mm] = __float2half_rn(ts[mm * 97 + v]);
    }
}

// ===== K3: peA =====
__global__ void __launch_bounds__(256) peA_build(const float* __restrict__ pe) {
    __shared__ float ts[128 * 17];
    int n = blockIdx.x >> 3, m0 = (blockIdx.x & 7) << 7;
    const float4* src = (const float4*)(pe + (size_t)n * 16384 + (size_t)m0 * 16);
#pragma unroll
    for (int i = 0; i < 2; i++) {
        int j = threadIdx.x + i * 256;
        float4 f = src[j];
        int e = j * 4, mm = e >> 4, k = e & 15;
        ts[mm * 17 + k] = f.x; ts[mm * 17 + k + 1] = f.y;
        ts[mm * 17 + k + 2] = f.z; ts[mm * 17 + k + 3] = f.w;
    }
    __syncthreads();
    int k = threadIdx.x >> 4, mq = threadIdx.x & 15;
    __align__(16) __half h8[8];
#pragma unroll
    for (int j = 0; j < 8; j++) h8[j] = __float2half_rn(ts[(mq * 8 + j) * 17 + k]);
    size_t off = ((size_t)n * 16 + k) * 1024 + m0 + mq * 8;
    *(uint4*)&g_peA[off] = *(const uint4*)h8;
}

// ===== K4: lamc — 512 blocks (b,k,part) =====
__global__ void __launch_bounds__(512) lamc_kernel() {
    __shared__ float ks[256];
    __shared__ float red[16][96];
    if (blockIdx.x == 0 && threadIdx.x == 0) g_tile = 296;
    int b = blockIdx.x >> 6, r = blockIdx.x & 63;
    int k = r >> 2, part = r & 3;
    int mbase = part * 256;
    const float* kr = g_proj + ((size_t)b * OT + OQ + k) * NNPX + mbase;
    if (threadIdx.x < 256) ks[threadIdx.x] = kr[threadIdx.x];
    __syncthreads();
    int w = threadIdx.x >> 5, lane = threadIdx.x & 31;
    const float* vb = g_vT + (size_t)b * NNPX * VS + (size_t)(mbase + w * 16) * VS;
    const float* kw = ks + w * 16;
    float a0 = 0.f, a1 = 0.f, a2 = 0.f;
#pragma unroll
    for (int mm = 0; mm < 16; mm++) {
        float kv = kw[mm];
        const float* row = vb + (size_t)mm * VS;
        a0 = fmaf(kv, __ldg(row + lane),      a0);
        a1 = fmaf(kv, __ldg(row + lane + 32), a1);
        a2 = fmaf(kv, __ldg(row + lane + 64), a2);
    }
    red[w][lane] = a0; red[w][lane + 32] = a1; red[w][lane + 64] = a2;
    __syncthreads();
    if (threadIdx.x < 96) {
        float s = 0.f;
#pragma unroll
        for (int i = 0; i < 16; i++) s += red[i][threadIdx.x];
        g_lamc4[(((size_t)b * KEYS + k) * VS + threadIdx.x) * 4 + part] = s;
    }
}

// ===== K5: lam_gemm — persistent, k64, 2-stage, next-tile prefetch over epilogue =====
#define PLSZ   18432
#define STSZ   36864
#define EB_OFF 73728           // epilogue buffer [16][132] = 8448B (own region!)
#define QS_OFF 82176
#define LS_OFF 98560
#define CTRL_OFF 106752
#define SMEM_REQ 106880
#define NTILES 768
#define NCTAS  296

__device__ __forceinline__ void load_stage(uint32_t sb, int g, int cc, int mc, int slot, int tid) {
    uint32_t st = sb + (uint32_t)slot * STSZ;
    const char* Ah = (const char*)g_peA + ((size_t)g * 128) * 2048 + mc * 128;
    const char* Bh = (const char*)g_vhf + ((size_t)cc * 128) * 2048 + mc * 128;
#pragma unroll
    for (int i = 0; i < 4; i++) {
        int a = tid + i * 256;
        int row = a >> 3, seg = a & 7;
        cp16(st + row * 144 + seg * 16, Ah + (size_t)row * 2048 + seg * 16);
        cp16(st + PLSZ + row * 144 + seg * 16, Bh + (size_t)row * 2048 + seg * 16);
    }
    cp_commit();
}

__global__ void __launch_bounds__(256, 2) lam_gemm(float* __restrict__ out) {
    extern __shared__ char sm[];
    uint32_t sb = smem_u32(sm);
    float* eb = (float*)(sm + EB_OFF);
    float* qs = (float*)(sm + QS_OFF);
    float* ls = (float*)(sm + LS_OFF);
    int* ctrl = (int*)(sm + CTRL_OFF);
    int tid = threadIdx.x, wid = tid >> 5, lane = tid & 31;
    int wr = wid & 3, wc = wid >> 2;
    int g4 = lane >> 2, i4 = lane & 3;

    uint32_t aAddr = sb + (uint32_t)((wr * 32 + (lane & 15)) * 144 + (lane >> 4) * 16);
    uint32_t bAddr = sb + PLSZ +
        (uint32_t)((wc * 64 + ((lane >> 4) << 3) + (lane & 7)) * 144 + ((lane >> 3) & 1) * 16);

    int t = blockIdx.x;
    if (t < NTILES) load_stage(sb, t / 6, t % 6, 0, 0, tid);

    while (t < NTILES) {
        int g = t / 6, cc = t - g * 6;
        int n0 = g * 8;

        for (int i = tid; i < BB * 8 * OQ; i += 256) {
            int o = i & 63, nn = (i >> 6) & 7, b = i >> 9;
            float val = g_proj[((size_t)b * OT + o) * NNPX + n0 + nn];
            qs[i] = fmaf(val, g_bnsc[o], g_bnsh[o]);
        }
        for (int i = tid; i < 128 * 16; i += 256) {
            int c = i >> 4, k = i & 15;
            int gcol = cc * 128 + c, b = gcol / 96, v = gcol - 96 * b;
            float4 p = *(const float4*)&g_lamc4[(((size_t)b * KEYS + k) * VS + v) * 4];
            ls[i] = (p.x + p.y) + (p.z + p.w);
        }

        float acc[2][8][4];
#pragma unroll
        for (int rt = 0; rt < 2; rt++)
#pragma unroll
            for (int nt = 0; nt < 8; nt++)
#pragma unroll
                for (int j = 0; j < 4; j++) acc[rt][nt][j] = 0.f;

        for (int mc = 0; mc < 16; mc++) {
            int slot = mc & 1;
            cp_wait<0>();
            __syncthreads();
            if (mc < 15) load_stage(sb, g, cc, mc + 1, slot ^ 1, tid);
            uint32_t so = (uint32_t)slot * STSZ;
#pragma unroll
            for (int kc = 0; kc < 4; kc++) {
                uint32_t ah[2][4];
                ldmx4(ah[0], aAddr + so + kc * 32);
                ldmx4(ah[1], aAddr + so + kc * 32 + 16 * 144);
#pragma unroll
                for (int ntp = 0; ntp < 4; ntp++) {
                    uint32_t bh[4];
                    ldmx4(bh, bAddr + so + kc * 32 + ntp * 16 * 144);
#pragma unroll
                    for (int rt = 0; rt < 2; rt++) {
                        mma16816(acc[rt][2 * ntp],     ah[rt], bh[0], bh[1]);
                        mma16816(acc[rt][2 * ntp + 1], ah[rt], bh[2], bh[3]);
                    }
                }
            }
        }

        // next tile id + prefetch its stage 0 into slot 0 (consumed at mc=14, free)
        if (tid == 0) *ctrl = atomicAdd(&g_tile, 1);
        __syncthreads();
        int tn = *ctrl;
        if (tn < NTILES) load_stage(sb, tn / 6, tn % 6, 0, 0, tid);

        // epilogue in 8 blocks of 16 cols through eb (stage region untouched)
        for (int cb = 0; cb < 8; cb++) {
            if (wc == (cb >> 2)) {
                int base = (cb & 3) * 2;
#pragma unroll
                for (int u = 0; u < 2; u++) {
                    int nt = base + u;
#pragma unroll
                    for (int rt = 0; rt < 2; rt++) {
                        float* a = acc[rt][nt];
                        int r0 = wr * 32 + rt * 16 + g4;
                        int cg = wc * 64 + nt * 8 + 2 * i4;   // col within cc tile
                        int cl = u * 8 + 2 * i4;              // col within eb block
                        eb[cl * 132 + r0]           = a[0] + ls[cg * 16 + g4];
                        eb[(cl + 1) * 132 + r0]     = a[1] + ls[(cg + 1) * 16 + g4];
                        eb[cl * 132 + r0 + 8]       = a[2] + ls[cg * 16 + g4 + 8];
                        eb[(cl + 1) * 132 + r0 + 8] = a[3] + ls[(cg + 1) * 16 + g4 + 8];
                    }
                }
            }
            __syncthreads();
            {   // 256 threads: c(16) x h(4) x nn-pair(4)
                int c = tid >> 4, h = (tid >> 2) & 3, np = tid & 3;
                int gcol = cc * 128 + cb * 16 + c;
                int b = gcol / 96, v = gcol - 96 * b;
                float y0 = 0.f, y1 = 0.f;
#pragma unroll
                for (int k4 = 0; k4 < 4; k4++) {
                    float4 l0 = *(const float4*)&eb[c * 132 + (np * 2) * 16 + k4 * 4];
                    float4 l1 = *(const float4*)&eb[c * 132 + (np * 2 + 1) * 16 + k4 * 4];
                    float4 q0 = *(const float4*)&qs[(b * 8 + np * 2) * 64 + h * 16 + k4 * 4];
                    float4 q1 = *(const float4*)&qs[(b * 8 + np * 2 + 1) * 64 + h * 16 + k4 * 4];
                    y0 = fmaf(l0.x, q0.x, fmaf(l0.y, q0.y, fmaf(l0.z, q0.z, fmaf(l0.w, q0.w, y0))));
                    y1 = fmaf(l1.x, q1.x, fmaf(l1.y, q1.y, fmaf(l1.z, q1.z, fmaf(l1.w, q1.w, y1))));
                }
                float* ob = out + ((size_t)(b * CC + h * VS + v)) * NNPX + n0 + np * 2;
                *(float2*)ob = make_float2(y0, y1);
            }
            __syncthreads();
        }
        t = tn;
    }
}

extern "C" void kernel_launch(void* const* d_in, const int* in_sizes, int n_in,
                              void* d_out, int out_size) {
    const float* x  = (const float*)d_in[0];
    const float* Wq = (const float*)d_in[1];
    const float* Wk = (const float*)d_in[2];
    const float* Wv = (const float*)d_in[3];
    const float* gq = (const float*)d_in[4];
    const float* bq = (const float*)d_in[5];
    const float* gv = (const float*)d_in[6];
    const float* bv = (const float*)d_in[7];
    const float* pe = (const float*)d_in[8];
    float* out = (float*)d_out;

    const int proj_smem = CC * 64 * (int)sizeof(float);
    cudaFuncSetAttribute(proj_kernel, cudaFuncAttributeMaxDynamicSharedMemorySize, proj_smem);
    cudaFuncSetAttribute(lam_gemm, cudaFuncAttributeMaxDynamicSharedMemorySize, SMEM_REQ);

    proj_kernel<<<128, 256, proj_smem>>>(x, Wq, Wk, Wv);   // idx 0
    bnsm_kernel<<<288, 256>>>(gq, bq, gv, bv);             // idx 1
    vT_build<<<256, 256>>>();                              // idx 2
    peA_build<<<8192, 256>>>(pe);                          // idx 3 -> ncu slot
    lamc_kernel<<<512, 512>>>();                           // idx 4
    lam_gemm<<<NCTAS, 256, SMEM_REQ>>>(out);               // idx 5
}

// round 15
// speedup vs baseline: 1.0593x; 1.0593x over previous
#include <cuda_runtime.h>
#include <cuda_fp16.h>
#include <cstdint>

#define BB 8
#define CC 384
#define NNPX 1024
#define KEYS 16
#define HEADS 4
#define VS 96
#define OQ 64
#define OKCH 16
#define OT 176

__device__ float g_proj[BB * OT * NNPX];
__device__ float g_vT[BB * NNPX * VS];
__device__ float g_lamc4[BB * KEYS * VS * 4];
__device__ float g_bnsc[160];
__device__ float g_bnsh[160];
__device__ int   g_tile;
__device__ __align__(16) __half g_peA[16384 * 1024];  // [(n*16+k)][m]
__device__ __align__(16) __half g_vhf[768 * 1024];    // [(b*96+v)][m]

__device__ __forceinline__ uint32_t smem_u32(const void* p) {
    uint32_t a;
    asm("{ .reg .u64 t; cvta.to.shared.u64 t, %1; cvt.u32.u64 %0, t; }" : "=r"(a) : "l"(p));
    return a;
}
__device__ __forceinline__ void cp16(uint32_t d, const void* s) {
    asm volatile("cp.async.cg.shared.global [%0], [%1], 16;" :: "r"(d), "l"(s) : "memory");
}
__device__ __forceinline__ void cp_commit() { asm volatile("cp.async.commit_group;" ::: "memory"); }
template <int N> __device__ __forceinline__ void cp_wait() {
    asm volatile("cp.async.wait_group %0;" :: "n"(N) : "memory");
}
__device__ __forceinline__ void ldmx4(uint32_t* r, uint32_t a) {
    asm volatile("ldmatrix.sync.aligned.m8n8.x4.shared.b16 {%0,%1,%2,%3}, [%4];"
                 : "=r"(r[0]), "=r"(r[1]), "=r"(r[2]), "=r"(r[3]) : "r"(a));
}
__device__ __forceinline__ void mma16816(float* d, const uint32_t* a, uint32_t b0, uint32_t b1) {
    asm volatile("mma.sync.aligned.m16n8k16.row.col.f32.f16.f16.f32 "
                 "{%0,%1,%2,%3}, {%4,%5,%6,%7}, {%8,%9}, {%0,%1,%2,%3};"
                 : "+f"(d[0]), "+f"(d[1]), "+f"(d[2]), "+f"(d[3])
                 : "r"(a[0]), "r"(a[1]), "r"(a[2]), "r"(a[3]), "r"(b0), "r"(b1));
}
__device__ __forceinline__ unsigned long long fma2(unsigned long long a,
                                                   unsigned long long b,
                                                   unsigned long long c) {
    unsigned long long d;
    asm("fma.rn.f32x2 %0, %1, %2, %3;" : "=l"(d) : "l"(a), "l"(b), "l"(c));
    return d;
}
__device__ __forceinline__ unsigned long long pack2(float lo, float hi) {
    unsigned long long d;
    asm("mov.b64 %0, {%1, %2};" : "=l"(d) : "f"(lo), "f"(hi));
    return d;
}
__device__ __forceinline__ void unpack2(unsigned long long d, float& lo, float& hi) {
    asm("mov.b64 {%0, %1}, %2;" : "=f"(lo), "=f"(hi) : "l"(d));
}

// ===== K0: proj (f32x2-packed) =====
__global__ void __launch_bounds__(256) proj_kernel(
    const float* __restrict__ x, const float* __restrict__ Wq,
    const float* __restrict__ Wk, const float* __restrict__ Wv) {
    extern __shared__ float xs[];
    int b = blockIdx.x >> 4, n0 = (blockIdx.x & 15) << 6;
    const float* xb = x + (size_t)b * CC * NNPX;
    for (int i = threadIdx.x; i < CC * 16; i += 256) {
        int c = i >> 4, q4 = i & 15;
        ((float4*)xs)[i] = *(const float4*)(xb + (size_t)c * NNPX + n0 + q4 * 4);
    }
    __syncthreads();
    int nq = threadIdx.x & 15, og = threadIdx.x >> 4;
    const float* wp[11];
#pragma unroll
    for (int j = 0; j < 11; j++) {
        int o = og * 11 + j;
        wp[j] = (o < OQ) ? (Wq + (size_t)o * CC)
              : ((o < OQ + OKCH) ? (Wk + (size_t)(o - OQ) * CC)
                                 : (Wv + (size_t)(o - OQ - OKCH) * CC));
    }
    unsigned long long acc[11][2];
#pragma unroll
    for (int j = 0; j < 11; j++) acc[j][0] = acc[j][1] = 0ull;
    for (int c = 0; c < CC; c++) {
        float4 xv = *(const float4*)(xs + c * 64 + nq * 4);
        unsigned long long x01 = pack2(xv.x, xv.y);
        unsigned long long x23 = pack2(xv.z, xv.w);
#pragma unroll
        for (int j = 0; j < 11; j++) {
            float w = __ldg(wp[j] + c);
            unsigned long long ww = pack2(w, w);
            acc[j][0] = fma2(ww, x01, acc[j][0]);
            acc[j][1] = fma2(ww, x23, acc[j][1]);
        }
    }
#pragma unroll
    for (int j = 0; j < 11; j++) {
        int o = og * 11 + j;
        float4 v4;
        unpack2(acc[j][0], v4.x, v4.y);
        unpack2(acc[j][1], v4.z, v4.w);
        *(float4*)(g_proj + ((size_t)b * OT + o) * NNPX + n0 + nq * 4) = v4;
    }
}

// ===== K1: fused BN stats + softmax =====
__global__ void __launch_bounds__(256) bnsm_kernel(
    const float* __restrict__ gq, const float* __restrict__ bq,
    const float* __restrict__ gv, const float* __restrict__ bv) {
    if (blockIdx.x < 160) {
        int ch = blockIdx.x;
        int o = (ch < OQ) ? ch : (OQ + OKCH + (ch - OQ));
        float s = 0.f, s2 = 0.f;
        for (int i = threadIdx.x; i < BB * NNPX; i += 256) {
            int b = i >> 10, n = i & (NNPX - 1);
            float v = g_proj[((size_t)b * OT + o) * NNPX + n];
            s += v; s2 = fmaf(v, v, s2);
        }
        __shared__ float rs[8], rs2[8];
#pragma unroll
        for (int off = 16; off; off >>= 1) {
            s += __shfl_xor_sync(~0u, s, off);
            s2 += __shfl_xor_sync(~0u, s2, off);
        }
        if ((threadIdx.x & 31) == 0) { rs[threadIdx.x >> 5] = s; rs2[threadIdx.x >> 5] = s2; }
        __syncthreads();
        if (threadIdx.x == 0) {
            float S = 0.f, S2 = 0.f;
#pragma unroll
            for (int i = 0; i < 8; i++) { S += rs[i]; S2 += rs2[i]; }
            const float inv = 1.f / (float)(BB * NNPX);
            float mean = S * inv, var = S2 * inv - mean * mean;
            float g = (ch < OQ) ? gq[ch] : gv[ch - OQ];
            float be = (ch < OQ) ? bq[ch] : bv[ch - OQ];
            float sc = g * rsqrtf(var + 1e-5f);
            g_bnsc[ch] = sc;
            g_bnsh[ch] = be - mean * sc;
        }
    } else {
        int blk = blockIdx.x - 160;
        int b = blk >> 4, key = blk & 15;
        float* row = g_proj + ((size_t)b * OT + OQ + key) * NNPX;
        int t = threadIdx.x;
        float4 v = *(float4*)(row + t * 4);
        float mx = fmaxf(fmaxf(v.x, v.y), fmaxf(v.z, v.w));
        __shared__ float rbuf[8];
#pragma unroll
        for (int off = 16; off; off >>= 1) mx = fmaxf(mx, __shfl_xor_sync(~0u, mx, off));
        if ((t & 31) == 0) rbuf[t >> 5] = mx;
        __syncthreads();
        mx = rbuf[0];
#pragma unroll
        for (int i = 1; i < 8; i++) mx = fmaxf(mx, rbuf[i]);
        float e0 = expf(v.x - mx), e1 = expf(v.y - mx), e2 = expf(v.z - mx), e3 = expf(v.w - mx);
        float s = e0 + e1 + e2 + e3;
#pragma unroll
        for (int off = 16; off; off >>= 1) s += __shfl_xor_sync(~0u, s, off);
        __syncthreads();
        if ((t & 31) == 0) rbuf[t >> 5] = s;
        __syncthreads();
        float S = 0.f;
#pragma unroll
        for (int i = 0; i < 8; i++) S += rbuf[i];
        float inv = 1.f / S;
        *(float4*)(row + t * 4) = make_float4(e0 * inv, e1 * inv, e2 * inv, e3 * inv);
    }
}

// ===== K2: vT fp32 + fp16 B plane =====
__global__ void __launch_bounds__(256) vT_build() {
    int b = blockIdx.x >> 5, m0 = (blockIdx.x & 31) << 5;
    __shared__ float ts[32 * 97];
    for (int i = threadIdx.x; i < VS * 32; i += 256) {
        int v = i >> 5, mm = i & 31;
        float val = g_proj[((size_t)b * OT + OQ + OKCH + v) * NNPX + m0 + mm];
        ts[mm * 97 + v] = fmaf(val, g_bnsc[64 + v], g_bnsh[64 + v]);
    }
    __syncthreads();
    for (int j = threadIdx.x; j < 32 * VS; j += 256) {
        int mm = j / VS, v = j - mm * VS;
        g_vT[((size_t)b * NNPX + m0 + mm) * VS + v] = ts[mm * 97 + v];
    }
    for (int j = threadIdx.x; j < VS * 32; j += 256) {
        int v = j >> 5, mm = j & 31;
        g_vhf[((size_t)(b * VS + v)) * 1024 + m0 + mm] = __float2half_rn(ts[mm * 97 + v]);
    }
}

// ===== K3: peA =====
__global__ void __launch_bounds__(256) peA_build(const float* __restrict__ pe) {
    __shared__ float ts[128 * 17];
    int n = blockIdx.x >> 3, m0 = (blockIdx.x & 7) << 7;
    const float4* src = (const float4*)(pe + (size_t)n * 16384 + (size_t)m0 * 16);
#pragma unroll
    for (int i = 0; i < 2; i++) {
        int j = threadIdx.x + i * 256;
        float4 f = src[j];
        int e = j * 4, mm = e >> 4, k = e & 15;
        ts[mm * 17 + k] = f.x; ts[mm * 17 + k + 1] = f.y;
        ts[mm * 17 + k + 2] = f.z; ts[mm * 17 + k + 3] = f.w;
    }
    __syncthreads();
    int k = threadIdx.x >> 4, mq = threadIdx.x & 15;
    __align__(16) __half h8[8];
#pragma unroll
    for (int j = 0; j < 8; j++) h8[j] = __float2half_rn(ts[(mq * 8 + j) * 17 + k]);
    size_t off = ((size_t)n * 16 + k) * 1024 + m0 + mq * 8;
    *(uint4*)&g_peA[off] = *(const uint4*)h8;
}

// ===== K4: lamc — 512 blocks (b,k,part) =====
__global__ void __launch_bounds__(512) lamc_kernel() {
    __shared__ float ks[256];
    __shared__ float red[16][96];
    if (blockIdx.x == 0 && threadIdx.x == 0) g_tile = 296;
    int b = blockIdx.x >> 6, r = blockIdx.x & 63;
    int k = r >> 2, part = r & 3;
    int mbase = part * 256;
    const float* kr = g_proj + ((size_t)b * OT + OQ + k) * NNPX + mbase;
    if (threadIdx.x < 256) ks[threadIdx.x] = kr[threadIdx.x];
    __syncthreads();
    int w = threadIdx.x >> 5, lane = threadIdx.x & 31;
    const float* vb = g_vT + (size_t)b * NNPX * VS + (size_t)(mbase + w * 16) * VS;
    const float* kw = ks + w * 16;
    float a0 = 0.f, a1 = 0.f, a2 = 0.f;
#pragma unroll
    for (int mm = 0; mm < 16; mm++) {
        float kv = kw[mm];
        const float* row = vb + (size_t)mm * VS;
        a0 = fmaf(kv, __ldg(row + lane),      a0);
        a1 = fmaf(kv, __ldg(row + lane + 32), a1);
        a2 = fmaf(kv, __ldg(row + lane + 64), a2);
    }
    red[w][lane] = a0; red[w][lane + 32] = a1; red[w][lane + 64] = a2;
    __syncthreads();
    if (threadIdx.x < 96) {
        float s = 0.f;
#pragma unroll
        for (int i = 0; i < 16; i++) s += red[i][threadIdx.x];
        g_lamc4[(((size_t)b * KEYS + k) * VS + threadIdx.x) * 4 + part] = s;
    }
}

// ===== K5: lam_gemm — R13 structure; prologue under load shadow, early tile fetch =====
#define PLSZ   18432
#define STSZ   36864
#define QS_OFF 73728
#define LS_OFF 90112
#define CTRL_OFF 98304
#define SMEM_REQ 98432
#define NTILES 768
#define NCTAS  296

__device__ __forceinline__ void load_stage(uint32_t sb, int g, int cc, int mc, int slot, int tid) {
    uint32_t st = sb + (uint32_t)slot * STSZ;
    const char* Ah = (const char*)g_peA + ((size_t)g * 128) * 2048 + mc * 128;
    const char* Bh = (const char*)g_vhf + ((size_t)cc * 128) * 2048 + mc * 128;
#pragma unroll
    for (int i = 0; i < 4; i++) {
        int a = tid + i * 256;
        int row = a >> 3, seg = a & 7;
        cp16(st + row * 144 + seg * 16, Ah + (size_t)row * 2048 + seg * 16);
        cp16(st + PLSZ + row * 144 + seg * 16, Bh + (size_t)row * 2048 + seg * 16);
    }
    cp_commit();
}

__global__ void __launch_bounds__(256, 2) lam_gemm(float* __restrict__ out) {
    extern __shared__ char sm[];
    uint32_t sb = smem_u32(sm);
    float* qs = (float*)(sm + QS_OFF);
    float* ls = (float*)(sm + LS_OFF);
    int* ctrl = (int*)(sm + CTRL_OFF);
    int tid = threadIdx.x, wid = tid >> 5, lane = tid & 31;
    int wr = wid & 3, wc = wid >> 2;

    uint32_t aAddr = sb + (uint32_t)((wr * 32 + (lane & 15)) * 144 + (lane >> 4) * 16);
    uint32_t bAddr = sb + PLSZ +
        (uint32_t)((wc * 64 + ((lane >> 4) << 3) + (lane & 7)) * 144 + ((lane >> 3) & 1) * 16);

    int t = blockIdx.x;
    while (t < NTILES) {
        int g = t / 6, cc = t - g * 6;
        int n0 = g * 8;

        // stage-0 load first: the qs/ls prologue below runs under its shadow
        load_stage(sb, g, cc, 0, 0, tid);

        for (int i = tid; i < BB * 8 * OQ; i += 256) {
            int o = i & 63, nn = (i >> 6) & 7, b = i >> 9;
            float val = g_proj[((size_t)b * OT + o) * NNPX + n0 + nn];
            qs[i] = fmaf(val, g_bnsc[o], g_bnsh[o]);
        }
        for (int i = tid; i < 128 * 16; i += 256) {
            int c = i >> 4, k = i & 15;
            int gcol = cc * 128 + c, b = gcol / 96, v = gcol - 96 * b;
            float4 p = *(const float4*)&g_lamc4[(((size_t)b * KEYS + k) * VS + v) * 4];
            ls[i] = (p.x + p.y) + (p.z + p.w);
        }

        float acc[2][8][4];
#pragma unroll
        for (int rt = 0; rt < 2; rt++)
#pragma unroll
            for (int nt = 0; nt < 8; nt++)
#pragma unroll
                for (int j = 0; j < 4; j++) acc[rt][nt][j] = 0.f;

        for (int mc = 0; mc < 16; mc++) {
            int slot = mc & 1;
            cp_wait<0>();
            __syncthreads();
            if (mc < 15) load_stage(sb, g, cc, mc + 1, slot ^ 1, tid);
            uint32_t so = (uint32_t)slot * STSZ;
#pragma unroll
            for (int kc = 0; kc < 4; kc++) {
                uint32_t ah[2][4];
                ldmx4(ah[0], aAddr + so + kc * 32);
                ldmx4(ah[1], aAddr + so + kc * 32 + 16 * 144);
#pragma unroll
                for (int ntp = 0; ntp < 4; ntp++) {
                    uint32_t bh[4];
                    ldmx4(bh, bAddr + so + kc * 32 + ntp * 16 * 144);
#pragma unroll
                    for (int rt = 0; rt < 2; rt++) {
                        mma16816(acc[rt][2 * ntp],     ah[rt], bh[0], bh[1]);
                        mma16816(acc[rt][2 * ntp + 1], ah[rt], bh[2], bh[3]);
                    }
                }
            }
        }
        // early next-tile fetch: atomic latency hides behind the epilogue
        if (tid == 0) *ctrl = atomicAdd(&g_tile, 1);
        __syncthreads();   // also orders: compute done before lamb overwrites stages
        int tn = *ctrl;

        float* lamb = (float*)sm;
        int g4 = lane >> 2, i4 = lane & 3;
#pragma unroll
        for (int rt = 0; rt < 2; rt++)
#pragma unroll
            for (int nt = 0; nt < 8; nt++) {
                int r0 = wr * 32 + rt * 16 + g4;
                int c0 = wc * 64 + nt * 8 + 2 * i4;
                float* a = acc[rt][nt];
                lamb[c0 * 132 + r0]           = a[0] + ls[c0 * 16 + g4];
                lamb[(c0 + 1) * 132 + r0]     = a[1] + ls[(c0 + 1) * 16 + g4];
                lamb[c0 * 132 + r0 + 8]       = a[2] + ls[c0 * 16 + g4 + 8];
                lamb[(c0 + 1) * 132 + r0 + 8] = a[3] + ls[(c0 + 1) * 16 + g4 + 8];
            }
        __syncthreads();

#pragma unroll
        for (int rep = 0; rep < 2; rep++) {
            int combo = tid * 2 + rep;
            int c = combo >> 2, h = combo & 3;
            int gcol = cc * 128 + c, b = gcol / 96, v = gcol - 96 * b;
            float y[8];
#pragma unroll
            for (int nn = 0; nn < 8; nn++) {
                float s0 = 0.f;
#pragma unroll
                for (int k4 = 0; k4 < 4; k4++) {
                    float4 l4 = *(const float4*)&lamb[c * 132 + nn * 16 + k4 * 4];
                    float4 q4 = *(const float4*)&qs[(b * 8 + nn) * 64 + h * 16 + k4 * 4];
                    s0 = fmaf(l4.x, q4.x, fmaf(l4.y, q4.y, fmaf(l4.z, q4.z, fmaf(l4.w, q4.w, s0))));
                }
                y[nn] = s0;
            }
            float* ob = out + ((size_t)(b * CC + h * VS + v)) * NNPX + n0;
            *(float4*)ob       = make_float4(y[0], y[1], y[2], y[3]);
            *(float4*)(ob + 4) = make_float4(y[4], y[5], y[6], y[7]);
        }
        __syncthreads();   // lamb reads done before next tile's stage-0 load reuses region
        t = tn;
    }
}

extern "C" void kernel_launch(void* const* d_in, const int* in_sizes, int n_in,
                              void* d_out, int out_size) {
    const float* x  = (const float*)d_in[0];
    const float* Wq = (const float*)d_in[1];
    const float* Wk = (const float*)d_in[2];
    const float* Wv = (const float*)d_in[3];
    const float* gq = (const float*)d_in[4];
    const float* bq = (const float*)d_in[5];
    const float* gv = (const float*)d_in[6];
    const float* bv = (const float*)d_in[7];
    const float* pe = (const float*)d_in[8];
    float* out = (float*)d_out;

    const int proj_smem = CC * 64 * (int)sizeof(float);
    cudaFuncSetAttribute(proj_kernel, cudaFuncAttributeMaxDynamicSharedMemorySize, proj_smem);
    cudaFuncSetAttribute(lam_gemm, cudaFuncAttributeMaxDynamicSharedMemorySize, SMEM_REQ);

    proj_kernel<<<128, 256, proj_smem>>>(x, Wq, Wk, Wv);   // idx 0
    bnsm_kernel<<<288, 256>>>(gq, bq, gv, bv);             // idx 1
    vT_build<<<256, 256>>>();                              // idx 2
    peA_build<<<8192, 256>>>(pe);                          // idx 3 -> ncu slot
    lamc_kernel<<<512, 512>>>();                           // idx 4
    lam_gemm<<<NCTAS, 256, SMEM_REQ>>>(out);               // idx 5
}

// round 16
// speedup vs baseline: 1.5963x; 1.5069x over previous
#include <cuda_runtime.h>
#include <cuda_fp16.h>
#include <cstdint>

#define BB 8
#define CC 384
#define NNPX 1024
#define KEYS 16
#define HEADS 4
#define VS 96
#define OQ 64
#define OKCH 16
#define OT 176

__device__ float g_proj[BB * OT * NNPX];
__device__ float g_vT[BB * NNPX * VS];
__device__ float g_lamc4[BB * KEYS * VS * 4];   // [(b*16+k)*96+v][part]
__device__ float g_bnsc[160];
__device__ float g_bnsh[160];
__device__ int   g_tile;
__device__ __align__(16) __half g_peA[16384 * 1024];  // [(n*16+k)][m] fp16
__device__ __align__(16) __half g_vhf[768 * 1024];    // [(b*96+v)][m] fp16

__device__ __forceinline__ uint32_t smem_u32(const void* p) {
    uint32_t a;
    asm("{ .reg .u64 t; cvta.to.shared.u64 t, %1; cvt.u32.u64 %0, t; }" : "=r"(a) : "l"(p));
    return a;
}
__device__ __forceinline__ void cp16(uint32_t d, const void* s) {
    asm volatile("cp.async.cg.shared.global [%0], [%1], 16;" :: "r"(d), "l"(s) : "memory");
}
__device__ __forceinline__ void cp_commit() { asm volatile("cp.async.commit_group;" ::: "memory"); }
template <int N> __device__ __forceinline__ void cp_wait() {
    asm volatile("cp.async.wait_group %0;" :: "n"(N) : "memory");
}
__device__ __forceinline__ void ldmx4(uint32_t* r, uint32_t a) {
    asm volatile("ldmatrix.sync.aligned.m8n8.x4.shared.b16 {%0,%1,%2,%3}, [%4];"
                 : "=r"(r[0]), "=r"(r[1]), "=r"(r[2]), "=r"(r[3]) : "r"(a));
}
__device__ __forceinline__ void mma16816(float* d, const uint32_t* a, uint32_t b0, uint32_t b1) {
    asm volatile("mma.sync.aligned.m16n8k16.row.col.f32.f16.f16.f32 "
                 "{%0,%1,%2,%3}, {%4,%5,%6,%7}, {%8,%9}, {%0,%1,%2,%3};"
                 : "+f"(d[0]), "+f"(d[1]), "+f"(d[2]), "+f"(d[3])
                 : "r"(a[0]), "r"(a[1]), "r"(a[2]), "r"(a[3]), "r"(b0), "r"(b1));
}
__device__ __forceinline__ unsigned long long fma2(unsigned long long a,
                                                   unsigned long long b,
                                                   unsigned long long c) {
    unsigned long long d;
    asm("fma.rn.f32x2 %0, %1, %2, %3;" : "=l"(d) : "l"(a), "l"(b), "l"(c));
    return d;
}
__device__ __forceinline__ unsigned long long pack2(float lo, float hi) {
    unsigned long long d;
    asm("mov.b64 %0, {%1, %2};" : "=l"(d) : "f"(lo), "f"(hi));
    return d;
}
__device__ __forceinline__ void unpack2(unsigned long long d, float& lo, float& hi) {
    asm("mov.b64 {%0, %1}, %2;" : "=f"(lo), "=f"(hi) : "l"(d));
}

// ===== K0: proj (f32x2-packed) =====
__global__ void __launch_bounds__(256) proj_kernel(
    const float* __restrict__ x, const float* __restrict__ Wq,
    const float* __restrict__ Wk, const float* __restrict__ Wv) {
    extern __shared__ float xs[];
    int b = blockIdx.x >> 4, n0 = (blockIdx.x & 15) << 6;
    const float* xb = x + (size_t)b * CC * NNPX;
    for (int i = threadIdx.x; i < CC * 16; i += 256) {
        int c = i >> 4, q4 = i & 15;
        ((float4*)xs)[i] = *(const float4*)(xb + (size_t)c * NNPX + n0 + q4 * 4);
    }
    __syncthreads();
    int nq = threadIdx.x & 15, og = threadIdx.x >> 4;
    const float* wp[11];
#pragma unroll
    for (int j = 0; j < 11; j++) {
        int o = og * 11 + j;
        wp[j] = (o < OQ) ? (Wq + (size_t)o * CC)
              : ((o < OQ + OKCH) ? (Wk + (size_t)(o - OQ) * CC)
                                 : (Wv + (size_t)(o - OQ - OKCH) * CC));
    }
    unsigned long long acc[11][2];
#pragma unroll
    for (int j = 0; j < 11; j++) acc[j][0] = acc[j][1] = 0ull;
    for (int c = 0; c < CC; c++) {
        float4 xv = *(const float4*)(xs + c * 64 + nq * 4);
        unsigned long long x01 = pack2(xv.x, xv.y);
        unsigned long long x23 = pack2(xv.z, xv.w);
#pragma unroll
        for (int j = 0; j < 11; j++) {
            float w = __ldg(wp[j] + c);
            unsigned long long ww = pack2(w, w);
            acc[j][0] = fma2(ww, x01, acc[j][0]);
            acc[j][1] = fma2(ww, x23, acc[j][1]);
        }
    }
#pragma unroll
    for (int j = 0; j < 11; j++) {
        int o = og * 11 + j;
        float4 v4;
        unpack2(acc[j][0], v4.x, v4.y);
        unpack2(acc[j][1], v4.z, v4.w);
        *(float4*)(g_proj + ((size_t)b * OT + o) * NNPX + n0 + nq * 4) = v4;
    }
}

// ===== K1: fused BN stats (blocks 0..159) + softmax (blocks 160..287) =====
__global__ void __launch_bounds__(256) bnsm_kernel(
    const float* __restrict__ gq, const float* __restrict__ bq,
    const float* __restrict__ gv, const float* __restrict__ bv) {
    if (blockIdx.x < 160) {
        int ch = blockIdx.x;
        int o = (ch < OQ) ? ch : (OQ + OKCH + (ch - OQ));
        float s = 0.f, s2 = 0.f;
        for (int i = threadIdx.x; i < BB * NNPX; i += 256) {
            int b = i >> 10, n = i & (NNPX - 1);
            float v = g_proj[((size_t)b * OT + o) * NNPX + n];
            s += v; s2 = fmaf(v, v, s2);
        }
        __shared__ float rs[8], rs2[8];
#pragma unroll
        for (int off = 16; off; off >>= 1) {
            s += __shfl_xor_sync(~0u, s, off);
            s2 += __shfl_xor_sync(~0u, s2, off);
        }
        if ((threadIdx.x & 31) == 0) { rs[threadIdx.x >> 5] = s; rs2[threadIdx.x >> 5] = s2; }
        __syncthreads();
        if (threadIdx.x == 0) {
            float S = 0.f, S2 = 0.f;
#pragma unroll
            for (int i = 0; i < 8; i++) { S += rs[i]; S2 += rs2[i]; }
            const float inv = 1.f / (float)(BB * NNPX);
            float mean = S * inv, var = S2 * inv - mean * mean;
            float g = (ch < OQ) ? gq[ch] : gv[ch - OQ];
            float be = (ch < OQ) ? bq[ch] : bv[ch - OQ];
            float sc = g * rsqrtf(var + 1e-5f);
            g_bnsc[ch] = sc;
            g_bnsh[ch] = be - mean * sc;
        }
    } else {
        int blk = blockIdx.x - 160;
        int b = blk >> 4, key = blk & 15;
        float* row = g_proj + ((size_t)b * OT + OQ + key) * NNPX;
        int t = threadIdx.x;
        float4 v = *(float4*)(row + t * 4);
        float mx = fmaxf(fmaxf(v.x, v.y), fmaxf(v.z, v.w));
        __shared__ float rbuf[8];
#pragma unroll
        for (int off = 16; off; off >>= 1) mx = fmaxf(mx, __shfl_xor_sync(~0u, mx, off));
        if ((t & 31) == 0) rbuf[t >> 5] = mx;
        __syncthreads();
        mx = rbuf[0];
#pragma unroll
        for (int i = 1; i < 8; i++) mx = fmaxf(mx, rbuf[i]);
        float e0 = expf(v.x - mx), e1 = expf(v.y - mx), e2 = expf(v.z - mx), e3 = expf(v.w - mx);
        float s = e0 + e1 + e2 + e3;
#pragma unroll
        for (int off = 16; off; off >>= 1) s += __shfl_xor_sync(~0u, s, off);
        __syncthreads();
        if ((t & 31) == 0) rbuf[t >> 5] = s;
        __syncthreads();
        float S = 0.f;
#pragma unroll
        for (int i = 0; i < 8; i++) S += rbuf[i];
        float inv = 1.f / S;
        *(float4*)(row + t * 4) = make_float4(e0 * inv, e1 * inv, e2 * inv, e3 * inv);
    }
}

// ===== K2: vT fp32 + fp16 B plane =====
__global__ void __launch_bounds__(256) vT_build() {
    int b = blockIdx.x >> 5, m0 = (blockIdx.x & 31) << 5;
    __shared__ float ts[32 * 97];
    for (int i = threadIdx.x; i < VS * 32; i += 256) {
        int v = i >> 5, mm = i & 31;
        float val = g_proj[((size_t)b * OT + OQ + OKCH + v) * NNPX + m0 + mm];
        ts[mm * 97 + v] = fmaf(val, g_bnsc[64 + v], g_bnsh[64 + v]);
    }
    __syncthreads();
    for (int j = threadIdx.x; j < 32 * VS; j += 256) {
        int mm = j / VS, v = j - mm * VS;
        g_vT[((size_t)b * NNPX + m0 + mm) * VS + v] = ts[mm * 97 + v];
    }
    for (int j = threadIdx.x; j < VS * 32; j += 256) {
        int v = j >> 5, mm = j & 31;
        g_vhf[((size_t)(b * VS + v)) * 1024 + m0 + mm] = __float2half_rn(ts[mm * 97 + v]);
    }
}

// ===== K3: peA — pe[n][m][k] -> fp16 plane [(n*16+k)][m]  (ncu slot 3; clock proxy) =====
__global__ void __launch_bounds__(256) peA_build(const float* __restrict__ pe) {
    __shared__ float ts[128 * 17];
    int n = blockIdx.x >> 3, m0 = (blockIdx.x & 7) << 7;
    const float4* src = (const float4*)(pe + (size_t)n * 16384 + (size_t)m0 * 16);
#pragma unroll
    for (int i = 0; i < 2; i++) {
        int j = threadIdx.x + i * 256;
        float4 f = src[j];
        int e = j * 4, mm = e >> 4, k = e & 15;
        ts[mm * 17 + k] = f.x; ts[mm * 17 + k + 1] = f.y;
        ts[mm * 17 + k + 2] = f.z; ts[mm * 17 + k + 3] = f.w;
    }
    __syncthreads();
    int k = threadIdx.x >> 4, mq = threadIdx.x & 15;
    __align__(16) __half h8[8];
#pragma unroll
    for (int j = 0; j < 8; j++) h8[j] = __float2half_rn(ts[(mq * 8 + j) * 17 + k]);
    size_t off = ((size_t)n * 16 + k) * 1024 + m0 + mq * 8;
    *(uint4*)&g_peA[off] = *(const uint4*)h8;
}

// ===== K4: lamc — 512 blocks (b,k,part), each reduces 256 m-rows =====
__global__ void __launch_bounds__(512) lamc_kernel() {
    __shared__ float ks[256];
    __shared__ float red[16][96];
    if (blockIdx.x == 0 && threadIdx.x == 0) g_tile = 296;  // persistent-GEMM counter
    int b = blockIdx.x >> 6, r = blockIdx.x & 63;
    int k = r >> 2, part = r & 3;
    int mbase = part * 256;
    const float* kr = g_proj + ((size_t)b * OT + OQ + k) * NNPX + mbase;
    if (threadIdx.x < 256) ks[threadIdx.x] = kr[threadIdx.x];
    __syncthreads();
    int w = threadIdx.x >> 5, lane = threadIdx.x & 31;
    const float* vb = g_vT + (size_t)b * NNPX * VS + (size_t)(mbase + w * 16) * VS;
    const float* kw = ks + w * 16;
    float a0 = 0.f, a1 = 0.f, a2 = 0.f;
#pragma unroll
    for (int mm = 0; mm < 16; mm++) {
        float kv = kw[mm];
        const float* row = vb + (size_t)mm * VS;
        a0 = fmaf(kv, __ldg(row + lane),      a0);
        a1 = fmaf(kv, __ldg(row + lane + 32), a1);
        a2 = fmaf(kv, __ldg(row + lane + 64), a2);
    }
    red[w][lane] = a0; red[w][lane + 32] = a1; red[w][lane + 64] = a2;
    __syncthreads();
    if (threadIdx.x < 96) {
        float s = 0.f;
#pragma unroll
        for (int i = 0; i < 16; i++) s += red[i][threadIdx.x];
        g_lamc4[(((size_t)b * KEYS + k) * VS + threadIdx.x) * 4 + part] = s;
    }
}

// ===== K5: lam_gemm — persistent, k64, 2-stage, R10 inner loop =====
#define PLSZ   18432          // 128 rows * 144B
#define STSZ   36864
#define QS_OFF 73728          // above stages AND above lamb (67584)
#define LS_OFF 90112
#define CTRL_OFF 98304
#define SMEM_REQ 98432
#define NTILES 768
#define NCTAS  296

__device__ __forceinline__ void load_stage(uint32_t sb, int g, int cc, int mc, int slot, int tid) {
    uint32_t st = sb + (uint32_t)slot * STSZ;
    const char* Ah = (const char*)g_peA + ((size_t)g * 128) * 2048 + mc * 128;
    const char* Bh = (const char*)g_vhf + ((size_t)cc * 128) * 2048 + mc * 128;
#pragma unroll
    for (int i = 0; i < 4; i++) {
        int a = tid + i * 256;
        int row = a >> 3, seg = a & 7;
        cp16(st + row * 144 + seg * 16, Ah + (size_t)row * 2048 + seg * 16);
        cp16(st + PLSZ + row * 144 + seg * 16, Bh + (size_t)row * 2048 + seg * 16);
    }
    cp_commit();
}

__global__ void __launch_bounds__(256, 2) lam_gemm(float* __restrict__ out) {
    extern __shared__ char sm[];
    uint32_t sb = smem_u32(sm);
    float* qs = (float*)(sm + QS_OFF);
    float* ls = (float*)(sm + LS_OFF);
    int* ctrl = (int*)(sm + CTRL_OFF);
    int tid = threadIdx.x, wid = tid >> 5, lane = tid & 31;
    int wr = wid & 3, wc = wid >> 2;

    uint32_t aAddr = sb + (uint32_t)((wr * 32 + (lane & 15)) * 144 + (lane >> 4) * 16);
    uint32_t bAddr = sb + PLSZ +
        (uint32_t)((wc * 64 + ((lane >> 4) << 3) + (lane & 7)) * 144 + ((lane >> 3) & 1) * 16);

    int t = blockIdx.x;
    while (t < NTILES) {
        int g = t / 6, cc = t - g * 6;
        int n0 = g * 8;

        for (int i = tid; i < BB * 8 * OQ; i += 256) {
            int o = i & 63, nn = (i >> 6) & 7, b = i >> 9;
            float val = g_proj[((size_t)b * OT + o) * NNPX + n0 + nn];
            qs[i] = fmaf(val, g_bnsc[o], g_bnsh[o]);
        }
        for (int i = tid; i < 128 * 16; i += 256) {
            int c = i >> 4, k = i & 15;
            int gcol = cc * 128 + c, b = gcol / 96, v = gcol - 96 * b;
            float4 p = *(const float4*)&g_lamc4[(((size_t)b * KEYS + k) * VS + v) * 4];
            ls[i] = (p.x + p.y) + (p.z + p.w);
        }

        float acc[2][8][4];
#pragma unroll
        for (int rt = 0; rt < 2; rt++)
#pragma unroll
            for (int nt = 0; nt < 8; nt++)
#pragma unroll
                for (int j = 0; j < 4; j++) acc[rt][nt][j] = 0.f;

        load_stage(sb, g, cc, 0, 0, tid);

        for (int mc = 0; mc < 16; mc++) {
            int slot = mc & 1;
            cp_wait<0>();
            __syncthreads();
            if (mc < 15) load_stage(sb, g, cc, mc + 1, slot ^ 1, tid);
            uint32_t so = (uint32_t)slot * STSZ;
#pragma unroll
            for (int kc = 0; kc < 4; kc++) {
                uint32_t ah[2][4];
                ldmx4(ah[0], aAddr + so + kc * 32);
                ldmx4(ah[1], aAddr + so + kc * 32 + 16 * 144);
#pragma unroll
                for (int ntp = 0; ntp < 4; ntp++) {
                    uint32_t bh[4];
                    ldmx4(bh, bAddr + so + kc * 32 + ntp * 16 * 144);
#pragma unroll
                    for (int rt = 0; rt < 2; rt++) {
                        mma16816(acc[rt][2 * ntp],     ah[rt], bh[0], bh[1]);
                        mma16816(acc[rt][2 * ntp + 1], ah[rt], bh[2], bh[3]);
                    }
                }
            }
        }
        __syncthreads();

        float* lamb = (float*)sm;
        int g4 = lane >> 2, i4 = lane & 3;
#pragma unroll
        for (int rt = 0; rt < 2; rt++)
#pragma unroll
            for (int nt = 0; nt < 8; nt++) {
                int r0 = wr * 32 + rt * 16 + g4;
                int c0 = wc * 64 + nt * 8 + 2 * i4;
                float* a = acc[rt][nt];
                lamb[c0 * 132 + r0]           = a[0] + ls[c0 * 16 + g4];
                lamb[(c0 + 1) * 132 + r0]     = a[1] + ls[(c0 + 1) * 16 + g4];
                lamb[c0 * 132 + r0 + 8]       = a[2] + ls[c0 * 16 + g4 + 8];
                lamb[(c0 + 1) * 132 + r0 + 8] = a[3] + ls[(c0 + 1) * 16 + g4 + 8];
            }
        __syncthreads();

#pragma unroll
        for (int rep = 0; rep < 2; rep++) {
            int combo = tid * 2 + rep;
            int c = combo >> 2, h = combo & 3;
            int gcol = cc * 128 + c, b = gcol / 96, v = gcol - 96 * b;
            float y[8];
#pragma unroll
            for (int nn = 0; nn < 8; nn++) {
                float s0 = 0.f;
#pragma unroll
                for (int k4 = 0; k4 < 4; k4++) {
                    float4 l4 = *(const float4*)&lamb[c * 132 + nn * 16 + k4 * 4];
                    float4 q4 = *(const float4*)&qs[(b * 8 + nn) * 64 + h * 16 + k4 * 4];
                    s0 = fmaf(l4.x, q4.x, fmaf(l4.y, q4.y, fmaf(l4.z, q4.z, fmaf(l4.w, q4.w, s0))));
                }
                y[nn] = s0;
            }
            float* ob = out + ((size_t)(b * CC + h * VS + v)) * NNPX + n0;
            *(float4*)ob       = make_float4(y[0], y[1], y[2], y[3]);
            *(float4*)(ob + 4) = make_float4(y[4], y[5], y[6], y[7]);
        }

        if (tid == 0) *ctrl = atomicAdd(&g_tile, 1);
        __syncthreads();
        t = *ctrl;
        __syncthreads();
    }
}

extern "C" void kernel_launch(void* const* d_in, const int* in_sizes, int n_in,
                              void* d_out, int out_size) {
    const float* x  = (const float*)d_in[0];
    const float* Wq = (const float*)d_in[1];
    const float* Wk = (const float*)d_in[2];
    const float* Wv = (const float*)d_in[3];
    const float* gq = (const float*)d_in[4];
    const float* bq = (const float*)d_in[5];
    const float* gv = (const float*)d_in[6];
    const float* bv = (const float*)d_in[7];
    const float* pe = (const float*)d_in[8];
    float* out = (float*)d_out;

    const int proj_smem = CC * 64 * (int)sizeof(float);
    cudaFuncSetAttribute(proj_kernel, cudaFuncAttributeMaxDynamicSharedMemorySize, proj_smem);
    cudaFuncSetAttribute(lam_gemm, cudaFuncAttributeMaxDynamicSharedMemorySize, SMEM_REQ);

    proj_kernel<<<128, 256, proj_smem>>>(x, Wq, Wk, Wv);   // idx 0
    bnsm_kernel<<<288, 256>>>(gq, bq, gv, bv);             // idx 1
    vT_build<<<256, 256>>>();                              // idx 2
    peA_build<<<8192, 256>>>(pe);                          // idx 3 -> ncu slot (clock proxy)
    lamc_kernel<<<512, 512>>>();                           // idx 4
    lam_gemm<<<NCTAS, 256, SMEM_REQ>>>(out);               // idx 5
}

// round 17
// speedup vs baseline: 1.6706x; 1.0466x over previous
#include <cuda_runtime.h>
#include <cuda_fp16.h>
#include <cstdint>

#define BB 8
#define CC 384
#define NNPX 1024
#define KEYS 16
#define HEADS 4
#define VS 96
#define OQ 64
#define OKCH 16
#define OT 176

__device__ float g_proj[BB * OT * NNPX];
__device__ float g_vT[BB * NNPX * VS];
__device__ float g_lamc4[BB * KEYS * VS * 4];
__device__ float g_bnsc[160];
__device__ float g_bnsh[160];
__device__ int   g_tile;
__device__ __align__(16) __half g_peA[16384 * 1024];  // [(n*16+k)][m]
__device__ __align__(16) __half g_vhf[768 * 1024];    // [(b*96+v)][m]

__device__ __forceinline__ uint32_t smem_u32(const void* p) {
    uint32_t a;
    asm("{ .reg .u64 t; cvta.to.shared.u64 t, %1; cvt.u32.u64 %0, t; }" : "=r"(a) : "l"(p));
    return a;
}
__device__ __forceinline__ void cp16(uint32_t d, const void* s) {
    asm volatile("cp.async.cg.shared.global [%0], [%1], 16;" :: "r"(d), "l"(s) : "memory");
}
__device__ __forceinline__ void cp_commit() { asm volatile("cp.async.commit_group;" ::: "memory"); }
template <int N> __device__ __forceinline__ void cp_wait() {
    asm volatile("cp.async.wait_group %0;" :: "n"(N) : "memory");
}
__device__ __forceinline__ void ldmx4(uint32_t* r, uint32_t a) {
    asm volatile("ldmatrix.sync.aligned.m8n8.x4.shared.b16 {%0,%1,%2,%3}, [%4];"
                 : "=r"(r[0]), "=r"(r[1]), "=r"(r[2]), "=r"(r[3]) : "r"(a));
}
__device__ __forceinline__ void mma16816(float* d, const uint32_t* a, uint32_t b0, uint32_t b1) {
    asm volatile("mma.sync.aligned.m16n8k16.row.col.f32.f16.f16.f32 "
                 "{%0,%1,%2,%3}, {%4,%5,%6,%7}, {%8,%9}, {%0,%1,%2,%3};"
                 : "+f"(d[0]), "+f"(d[1]), "+f"(d[2]), "+f"(d[3])
                 : "r"(a[0]), "r"(a[1]), "r"(a[2]), "r"(a[3]), "r"(b0), "r"(b1));
}
__device__ __forceinline__ unsigned long long fma2(unsigned long long a,
                                                   unsigned long long b,
                                                   unsigned long long c) {
    unsigned long long d;
    asm("fma.rn.f32x2 %0, %1, %2, %3;" : "=l"(d) : "l"(a), "l"(b), "l"(c));
    return d;
}
__device__ __forceinline__ unsigned long long pack2(float lo, float hi) {
    unsigned long long d;
    asm("mov.b64 %0, {%1, %2};" : "=l"(d) : "f"(lo), "f"(hi));
    return d;
}
__device__ __forceinline__ void unpack2(unsigned long long d, float& lo, float& hi) {
    asm("mov.b64 {%0, %1}, %2;" : "=f"(lo), "=f"(hi) : "l"(d));
}

// ===== K0: proj — 512 threads/block for 4 warps/SMSP (was 2) =====
__global__ void __launch_bounds__(512) proj_kernel(
    const float* __restrict__ x, const float* __restrict__ Wq,
    const float* __restrict__ Wk, const float* __restrict__ Wv) {
    extern __shared__ float xs[];  // [384][64]
    int b = blockIdx.x >> 4, n0 = (blockIdx.x & 15) << 6;
    const float* xb = x + (size_t)b * CC * NNPX;
    for (int i = threadIdx.x; i < CC * 16; i += 512) {
        int c = i >> 4, q4 = i & 15;
        ((float4*)xs)[i] = *(const float4*)(xb + (size_t)c * NNPX + n0 + q4 * 4);
    }
    __syncthreads();
    int nq = threadIdx.x & 15, og = threadIdx.x >> 4;   // 16 quads x 32 groups
    const float* wp[6];
    bool valid[6];
#pragma unroll
    for (int j = 0; j < 6; j++) {
        int o = og * 6 + j;
        valid[j] = (o < OT);
        int oc = valid[j] ? o : 0;
        wp[j] = (oc < OQ) ? (Wq + (size_t)oc * CC)
              : ((oc < OQ + OKCH) ? (Wk + (size_t)(oc - OQ) * CC)
                                  : (Wv + (size_t)(oc - OQ - OKCH) * CC));
    }
    unsigned long long acc[6][2];
#pragma unroll
    for (int j = 0; j < 6; j++) acc[j][0] = acc[j][1] = 0ull;
    for (int c = 0; c < CC; c++) {
        float4 xv = *(const float4*)(xs + c * 64 + nq * 4);
        unsigned long long x01 = pack2(xv.x, xv.y);
        unsigned long long x23 = pack2(xv.z, xv.w);
#pragma unroll
        for (int j = 0; j < 6; j++) {
            float w = __ldg(wp[j] + c);
            unsigned long long ww = pack2(w, w);
            acc[j][0] = fma2(ww, x01, acc[j][0]);
            acc[j][1] = fma2(ww, x23, acc[j][1]);
        }
    }
#pragma unroll
    for (int j = 0; j < 6; j++) {
        if (!valid[j]) continue;
        int o = og * 6 + j;
        float4 v4;
        unpack2(acc[j][0], v4.x, v4.y);
        unpack2(acc[j][1], v4.z, v4.w);
        *(float4*)(g_proj + ((size_t)b * OT + o) * NNPX + n0 + nq * 4) = v4;
    }
}

// ===== K1: fused BN stats (blocks 0..159) + softmax (blocks 160..287) =====
__global__ void __launch_bounds__(256) bnsm_kernel(
    const float* __restrict__ gq, const float* __restrict__ bq,
    const float* __restrict__ gv, const float* __restrict__ bv) {
    if (blockIdx.x < 160) {
        int ch = blockIdx.x;
        int o = (ch < OQ) ? ch : (OQ + OKCH + (ch - OQ));
        float s = 0.f, s2 = 0.f;
        for (int i = threadIdx.x; i < BB * NNPX; i += 256) {
            int b = i >> 10, n = i & (NNPX - 1);
            float v = g_proj[((size_t)b * OT + o) * NNPX + n];
            s += v; s2 = fmaf(v, v, s2);
        }
        __shared__ float rs[8], rs2[8];
#pragma unroll
        for (int off = 16; off; off >>= 1) {
            s += __shfl_xor_sync(~0u, s, off);
            s2 += __shfl_xor_sync(~0u, s2, off);
        }
        if ((threadIdx.x & 31) == 0) { rs[threadIdx.x >> 5] = s; rs2[threadIdx.x >> 5] = s2; }
        __syncthreads();
        if (threadIdx.x == 0) {
            float S = 0.f, S2 = 0.f;
#pragma unroll
            for (int i = 0; i < 8; i++) { S += rs[i]; S2 += rs2[i]; }
            const float inv = 1.f / (float)(BB * NNPX);
            float mean = S * inv, var = S2 * inv - mean * mean;
            float g = (ch < OQ) ? gq[ch] : gv[ch - OQ];
            float be = (ch < OQ) ? bq[ch] : bv[ch - OQ];
            float sc = g * rsqrtf(var + 1e-5f);
            g_bnsc[ch] = sc;
            g_bnsh[ch] = be - mean * sc;
        }
    } else {
        int blk = blockIdx.x - 160;
        int b = blk >> 4, key = blk & 15;
        float* row = g_proj + ((size_t)b * OT + OQ + key) * NNPX;
        int t = threadIdx.x;
        float4 v = *(float4*)(row + t * 4);
        float mx = fmaxf(fmaxf(v.x, v.y), fmaxf(v.z, v.w));
        __shared__ float rbuf[8];
#pragma unroll
        for (int off = 16; off; off >>= 1) mx = fmaxf(mx, __shfl_xor_sync(~0u, mx, off));
        if ((t & 31) == 0) rbuf[t >> 5] = mx;
        __syncthreads();
        mx = rbuf[0];
#pragma unroll
        for (int i = 1; i < 8; i++) mx = fmaxf(mx, rbuf[i]);
        float e0 = expf(v.x - mx), e1 = expf(v.y - mx), e2 = expf(v.z - mx), e3 = expf(v.w - mx);
        float s = e0 + e1 + e2 + e3;
#pragma unroll
        for (int off = 16; off; off >>= 1) s += __shfl_xor_sync(~0u, s, off);
        __syncthreads();
        if ((t & 31) == 0) rbuf[t >> 5] = s;
        __syncthreads();
        float S = 0.f;
#pragma unroll
        for (int i = 0; i < 8; i++) S += rbuf[i];
        float inv = 1.f / S;
        *(float4*)(row + t * 4) = make_float4(e0 * inv, e1 * inv, e2 * inv, e3 * inv);
    }
}

// ===== K2: vT fp32 + fp16 B plane =====
__global__ void __launch_bounds__(256) vT_build() {
    int b = blockIdx.x >> 5, m0 = (blockIdx.x & 31) << 5;
    __shared__ float ts[32 * 97];
    for (int i = threadIdx.x; i < VS * 32; i += 256) {
        int v = i >> 5, mm = i & 31;
        float val = g_proj[((size_t)b * OT + OQ + OKCH + v) * NNPX + m0 + mm];
        ts[mm * 97 + v] = fmaf(val, g_bnsc[64 + v], g_bnsh[64 + v]);
    }
    __syncthreads();
    for (int j = threadIdx.x; j < 32 * VS; j += 256) {
        int mm = j / VS, v = j - mm * VS;
        g_vT[((size_t)b * NNPX + m0 + mm) * VS + v] = ts[mm * 97 + v];
    }
    for (int j = threadIdx.x; j < VS * 32; j += 256) {
        int v = j >> 5, mm = j & 31;
        g_vhf[((size_t)(b * VS + v)) * 1024 + m0 + mm] = __float2half_rn(ts[mm * 97 + v]);
    }
}

// ===== K3: peA (ncu slot 3; clock canary ~20us at normal clocks) =====
__global__ void __launch_bounds__(256) peA_build(const float* __restrict__ pe) {
    __shared__ float ts[128 * 17];
    int n = blockIdx.x >> 3, m0 = (blockIdx.x & 7) << 7;
    const float4* src = (const float4*)(pe + (size_t)n * 16384 + (size_t)m0 * 16);
#pragma unroll
    for (int i = 0; i < 2; i++) {
        int j = threadIdx.x + i * 256;
        float4 f = src[j];
        int e = j * 4, mm = e >> 4, k = e & 15;
        ts[mm * 17 + k] = f.x; ts[mm * 17 + k + 1] = f.y;
        ts[mm * 17 + k + 2] = f.z; ts[mm * 17 + k + 3] = f.w;
    }
    __syncthreads();
    int k = threadIdx.x >> 4, mq = threadIdx.x & 15;
    __align__(16) __half h8[8];
#pragma unroll
    for (int j = 0; j < 8; j++) h8[j] = __float2half_rn(ts[(mq * 8 + j) * 17 + k]);
    size_t off = ((size_t)n * 16 + k) * 1024 + m0 + mq * 8;
    *(uint4*)&g_peA[off] = *(const uint4*)h8;
}

// ===== K4: lamc — 512 blocks (b,k,part) =====
__global__ void __launch_bounds__(512) lamc_kernel() {
    __shared__ float ks[256];
    __shared__ float red[16][96];
    if (blockIdx.x == 0 && threadIdx.x == 0) g_tile = 296;
    int b = blockIdx.x >> 6, r = blockIdx.x & 63;
    int k = r >> 2, part = r & 3;
    int mbase = part * 256;
    const float* kr = g_proj + ((size_t)b * OT + OQ + k) * NNPX + mbase;
    if (threadIdx.x < 256) ks[threadIdx.x] = kr[threadIdx.x];
    __syncthreads();
    int w = threadIdx.x >> 5, lane = threadIdx.x & 31;
    const float* vb = g_vT + (size_t)b * NNPX * VS + (size_t)(mbase + w * 16) * VS;
    const float* kw = ks + w * 16;
    float a0 = 0.f, a1 = 0.f, a2 = 0.f;
#pragma unroll
    for (int mm = 0; mm < 16; mm++) {
        float kv = kw[mm];
        const float* row = vb + (size_t)mm * VS;
        a0 = fmaf(kv, __ldg(row + lane),      a0);
        a1 = fmaf(kv, __ldg(row + lane + 32), a1);
        a2 = fmaf(kv, __ldg(row + lane + 64), a2);
    }
    red[w][lane] = a0; red[w][lane + 32] = a1; red[w][lane + 64] = a2;
    __syncthreads();
    if (threadIdx.x < 96) {
        float s = 0.f;
#pragma unroll
        for (int i = 0; i < 16; i++) s += red[i][threadIdx.x];
        g_lamc4[(((size_t)b * KEYS + k) * VS + threadIdx.x) * 4 + part] = s;
    }
}

// ===== K5: lam_gemm — persistent, k64, 2-stage, R10 inner loop (unchanged) =====
#define PLSZ   18432
#define STSZ   36864
#define QS_OFF 73728
#define LS_OFF 90112
#define CTRL_OFF 98304
#define SMEM_REQ 98432
#define NTILES 768
#define NCTAS  296

__device__ __forceinline__ void load_stage(uint32_t sb, int g, int cc, int mc, int slot, int tid) {
    uint32_t st = sb + (uint32_t)slot * STSZ;
    const char* Ah = (const char*)g_peA + ((size_t)g * 128) * 2048 + mc * 128;
    const char* Bh = (const char*)g_vhf + ((size_t)cc * 128) * 2048 + mc * 128;
#pragma unroll
    for (int i = 0; i < 4; i++) {
        int a = tid + i * 256;
        int row = a >> 3, seg = a & 7;
        cp16(st + row * 144 + seg * 16, Ah + (size_t)row * 2048 + seg * 16);
        cp16(st + PLSZ + row * 144 + seg * 16, Bh + (size_t)row * 2048 + seg * 16);
    }
    cp_commit();
}

__global__ void __launch_bounds__(256, 2) lam_gemm(float* __restrict__ out) {
    extern __shared__ char sm[];
    uint32_t sb = smem_u32(sm);
    float* qs = (float*)(sm + QS_OFF);
    float* ls = (float*)(sm + LS_OFF);
    int* ctrl = (int*)(sm + CTRL_OFF);
    int tid = threadIdx.x, wid = tid >> 5, lane = tid & 31;
    int wr = wid & 3, wc = wid >> 2;

    uint32_t aAddr = sb + (uint32_t)((wr * 32 + (lane & 15)) * 144 + (lane >> 4) * 16);
    uint32_t bAddr = sb + PLSZ +
        (uint32_t)((wc * 64 + ((lane >> 4) << 3) + (lane & 7)) * 144 + ((lane >> 3) & 1) * 16);

    int t = blockIdx.x;
    while (t < NTILES) {
        int g = t / 6, cc = t - g * 6;
        int n0 = g * 8;

        for (int i = tid; i < BB * 8 * OQ; i += 256) {
            int o = i & 63, nn = (i >> 6) & 7, b = i >> 9;
            float val = g_proj[((size_t)b * OT + o) * NNPX + n0 + nn];
            qs[i] = fmaf(val, g_bnsc[o], g_bnsh[o]);
        }
        for (int i = tid; i < 128 * 16; i += 256) {
            int c = i >> 4, k = i & 15;
            int gcol = cc * 128 + c, b = gcol / 96, v = gcol - 96 * b;
            float4 p = *(const float4*)&g_lamc4[(((size_t)b * KEYS + k) * VS + v) * 4];
            ls[i] = (p.x + p.y) + (p.z + p.w);
        }

        float acc[2][8][4];
#pragma unroll
        for (int rt = 0; rt < 2; rt++)
#pragma unroll
            for (int nt = 0; nt < 8; nt++)
#pragma unroll
                for (int j = 0; j < 4; j++) acc[rt][nt][j] = 0.f;

        load_stage(sb, g, cc, 0, 0, tid);

        for (int mc = 0; mc < 16; mc++) {
            int slot = mc & 1;
            cp_wait<0>();
            __syncthreads();
            if (mc < 15) load_stage(sb, g, cc, mc + 1, slot ^ 1, tid);
            uint32_t so = (uint32_t)slot * STSZ;
#pragma unroll
            for (int kc = 0; kc < 4; kc++) {
                uint32_t ah[2][4];
                ldmx4(ah[0], aAddr + so + kc * 32);
                ldmx4(ah[1], aAddr + so + kc * 32 + 16 * 144);
#pragma unroll
                for (int ntp = 0; ntp < 4; ntp++) {
                    uint32_t bh[4];
                    ldmx4(bh, bAddr + so + kc * 32 + ntp * 16 * 144);
#pragma unroll
                    for (int rt = 0; rt < 2; rt++) {
                        mma16816(acc[rt][2 * ntp],     ah[rt], bh[0], bh[1]);
                        mma16816(acc[rt][2 * ntp + 1], ah[rt], bh[2], bh[3]);
                    }
                }
            }
        }
        __syncthreads();

        float* lamb = (float*)sm;
        int g4 = lane >> 2, i4 = lane & 3;
#pragma unroll
        for (int rt = 0; rt < 2; rt++)
#pragma unroll
            for (int nt = 0; nt < 8; nt++) {
                int r0 = wr * 32 + rt * 16 + g4;
                int c0 = wc * 64 + nt * 8 + 2 * i4;
                float* a = acc[rt][nt];
                lamb[c0 * 132 + r0]           = a[0] + ls[c0 * 16 + g4];
                lamb[(c0 + 1) * 132 + r0]     = a[1] + ls[(c0 + 1) * 16 + g4];
                lamb[c0 * 132 + r0 + 8]       = a[2] + ls[c0 * 16 + g4 + 8];
                lamb[(c0 + 1) * 132 + r0 + 8] = a[3] + ls[(c0 + 1) * 16 + g4 + 8];
            }
        __syncthreads();

#pragma unroll
        for (int rep = 0; rep < 2; rep++) {
            int combo = tid * 2 + rep;
            int c = combo >> 2, h = combo & 3;
            int gcol = cc * 128 + c, b = gcol / 96, v = gcol - 96 * b;
            float y[8];
#pragma unroll
            for (int nn = 0; nn < 8; nn++) {
                float s0 = 0.f;
#pragma unroll
                for (int k4 = 0; k4 < 4; k4++) {
                    float4 l4 = *(const float4*)&lamb[c * 132 + nn * 16 + k4 * 4];
                    float4 q4 = *(const float4*)&qs[(b * 8 + nn) * 64 + h * 16 + k4 * 4];
                    s0 = fmaf(l4.x, q4.x, fmaf(l4.y, q4.y, fmaf(l4.z, q4.z, fmaf(l4.w, q4.w, s0))));
                }
                y[nn] = s0;
            }
            float* ob = out + ((size_t)(b * CC + h * VS + v)) * NNPX + n0;
            *(float4*)ob       = make_float4(y[0], y[1], y[2], y[3]);
            *(float4*)(ob + 4) = make_float4(y[4], y[5], y[6], y[7]);
        }

        if (tid == 0) *ctrl = atomicAdd(&g_tile, 1);
        __syncthreads();
        t = *ctrl;
        __syncthreads();
    }
}

extern "C" void kernel_launch(void* const* d_in, const int* in_sizes, int n_in,
                              void* d_out, int out_size) {
    const float* x  = (const float*)d_in[0];
    const float* Wq = (const float*)d_in[1];
    const float* Wk = (const float*)d_in[2];
    const float* Wv = (const float*)d_in[3];
    const float* gq = (const float*)d_in[4];
    const float* bq = (const float*)d_in[5];
    const float* gv = (const float*)d_in[6];
    const float* bv = (const float*)d_in[7];
    const float* pe = (const float*)d_in[8];
    float* out = (float*)d_out;

    const int proj_smem = CC * 64 * (int)sizeof(float);
    cudaFuncSetAttribute(proj_kernel, cudaFuncAttributeMaxDynamicSharedMemorySize, proj_smem);
    cudaFuncSetAttribute(lam_gemm, cudaFuncAttributeMaxDynamicSharedMemorySize, SMEM_REQ);

    proj_kernel<<<128, 512, proj_smem>>>(x, Wq, Wk, Wv);   // idx 0 (512 threads now)
    bnsm_kernel<<<288, 256>>>(gq, bq, gv, bv);             // idx 1
    vT_build<<<256, 256>>>();                              // idx 2
    peA_build<<<8192, 256>>>(pe);                          // idx 3 -> ncu slot (clock canary)
    lamc_kernel<<<512, 512>>>();                           // idx 4
    lam_gemm<<<NCTAS, 256, SMEM_REQ>>>(out);               // idx 5
}